// round 8
// baseline (speedup 1.0000x reference)
#include <cuda_runtime.h>
#include <cuda_fp16.h>

#define VN 100000
#define EN 1600000
#define BATCH 4
#define BN_EPS 1e-5f
#define NB_SCAN 98            // ceil(VN/1024)
#define G_HIST 6250           // (EN+255)/256
#define G_RS   391            // (VN+255)/256
#define G_STAT 2048           // 32 channels x 64 blocks
#define G_FILL 6250
#define G_APPL 1563           // (VN+63)/64
#define G_ZDEG 391

// ---------------- static device scratch (no allocations allowed) ----------------
// feature tensors fp16, layout (V, C, B): element (v,c,b) at ((v*C+c)*4+b)
__device__ __align__(256) __half g_XN[VN * 32 * BATCH];   // BN'ed input (x0 of layer 0)
__device__ __align__(256) __half g_R1[VN * 64 * BATCH];   // relu(H1) / b2
__device__ __align__(256) __half g_SA[VN * 64 * BATCH];   // x1 / y0^
__device__ __align__(256) __half g_SB[VN * 64 * BATCH];   // x2 / y1^
__device__ __align__(256) __half g_SC[VN * 64 * BATCH];   // x3 / y2^ / b1
__device__ __align__(256) __half g_R0[VN * 64 * BATCH];   // relu(H0) / y3^
__device__ float g_red[128];          // zero at call start (static init / finalize re-zeroes)
__device__ float g_scale[64];
__device__ float g_shift[64];

// folded weights / constant vectors
__device__ float g_wf[4 * 64 * 64];
__device__ float g_bf[64];
__device__ float g_wf2[4 * 64 * 32];
__device__ float g_qb2[32], g_pb2[32], g_qb1[32], g_qout[32];

// CSR scratch
__device__ __align__(256) int   g_deg[VN];      // zero at call start (static / re-zeroed in fill_apply)
__device__ __align__(256) int   g_rowptr[VN + 1];
__device__ __align__(256) int   g_cursor[VN];
__device__ __align__(256) float g_rowsum[VN];   // zeroed in hist_stats
__device__ __align__(256) int   g_ecol[EN];
__device__ __align__(256) float g_eval[EN];

// decoupled-lookback scan state (flags re-zeroed in fill_apply)
__device__ volatile int g_agg[NB_SCAN];
__device__ volatile int g_incl[NB_SCAN];
__device__ volatile int g_flag[NB_SCAN];        // 0 none, 1 agg ready, 2 incl ready

// ---------------- fp16 helpers (8 values = 2 channels x 4 batch) ----------------
__device__ __forceinline__ void fma8(float* acc, float w, uint4 q) {
    half2* h = (half2*)&q;
#pragma unroll
    for (int t = 0; t < 4; t++) {
        float2 f = __half22float2(h[t]);
        acc[2 * t]     += w * f.x;
        acc[2 * t + 1] += w * f.y;
    }
}
__device__ __forceinline__ void unpack8(float* z, uint4 q) {
    half2* h = (half2*)&q;
#pragma unroll
    for (int t = 0; t < 4; t++) {
        float2 f = __half22float2(h[t]);
        z[2 * t] = f.x; z[2 * t + 1] = f.y;
    }
}
__device__ __forceinline__ uint4 pack8(const float* r) {
    uint4 q;
    half2* h = (half2*)&q;
#pragma unroll
    for (int t = 0; t < 4; t++) h[t] = __floats2half2_rn(r[2 * t], r[2 * t + 1]);
    return q;
}

// ================= launch 1: edge histogram + input BN stats + zero rowsum =================
__global__ void __launch_bounds__(256) k_hist_stats(const int* __restrict__ rows,
                                                    const float* __restrict__ x) {
    int b = blockIdx.x;
    if (b < G_HIST) {
        int e = b * 256 + threadIdx.x;
        if (e < EN) atomicAdd(&g_deg[rows[e]], 1);
        return;
    }
    b -= G_HIST;
    if (b < G_RS) {
        int i = b * 256 + threadIdx.x;
        if (i < VN) g_rowsum[i] = 0.f;
        return;
    }
    b -= G_RS;
    // stats: b in [0, 2048): channel = b>>6, chunk = b&63
    int c = b >> 6;
    int chunk = b & 63;
    float s1 = 0.f, s2 = 0.f;
    for (int v = chunk * 256 + threadIdx.x; v < VN; v += 64 * 256) {
#pragma unroll
        for (int bb = 0; bb < BATCH; bb++) {
            float t = x[(bb * 32 + c) * VN + v];
            s1 += t; s2 += t * t;
        }
    }
    __shared__ float sh1[256], sh2[256];
    sh1[threadIdx.x] = s1; sh2[threadIdx.x] = s2;
    __syncthreads();
    for (int off = 128; off > 0; off >>= 1) {
        if (threadIdx.x < off) {
            sh1[threadIdx.x] += sh1[threadIdx.x + off];
            sh2[threadIdx.x] += sh2[threadIdx.x + off];
        }
        __syncthreads();
    }
    if (threadIdx.x == 0) {
        atomicAdd(&g_red[c], sh1[0]);
        atomicAdd(&g_red[64 + c], sh2[0]);
    }
}

// ================= launch 2: decoupled-lookback scan + input BN finalize =================
__global__ void __launch_bounds__(1024) k_scan() {
    int b = blockIdx.x;
    int t = threadIdx.x;
    if (b == NB_SCAN) {
        // input BN finalize (stats complete: previous launch) then zero g_red
        if (t < 32) {
            float n = (float)VN * (float)BATCH;
            float m = g_red[t] / n;
            float var = g_red[64 + t] / n - m * m;
            // gamma=1, beta=0 folded at host? NO: need gamma/beta... handled: input BN params
            // are applied in k_fill_apply via g_scale/g_shift computed HERE with params passed
            // through constant globals is not possible -> compute raw inv-std & mean here:
            g_scale[t] = rsqrtf(var + BN_EPS);   // raw inv-std (gamma applied in apply)
            g_shift[t] = m;                      // raw mean
        }
        __syncthreads();
        if (t < 128) g_red[t] = 0.f;
        if (t == 0) g_rowptr[VN] = EN;
        return;
    }
    __shared__ int sh[1024];
    int i = b * 1024 + t;
    int val = (i < VN) ? g_deg[i] : 0;
    sh[t] = val;
    __syncthreads();
    for (int off = 1; off < 1024; off <<= 1) {
        int tmp = (t >= off) ? sh[t - off] : 0;
        __syncthreads();
        sh[t] += tmp;
        __syncthreads();
    }
    __shared__ int s_prefix;
    if (t == 0) {
        int total = sh[1023];
        int prefix = 0;
        if (b == 0) {
            g_incl[0] = total;
            __threadfence();
            g_flag[0] = 2;
        } else {
            g_agg[b] = total;
            __threadfence();
            g_flag[b] = 1;
            int j = b - 1;
            while (true) {
                int f;
                while ((f = g_flag[j]) == 0) { }
                if (f == 2) { prefix += g_incl[j]; break; }
                prefix += g_agg[j];
                j--;
            }
            g_incl[b] = prefix + total;
            __threadfence();
            g_flag[b] = 2;
        }
        s_prefix = prefix;
    }
    __syncthreads();
    if (i < VN) {
        int excl = s_prefix + sh[t] - val;
        g_rowptr[i] = excl;
        g_cursor[i] = excl;
    }
}

// ================= launch 3: CSR fill + input BN apply/transpose + zero deg/flags =========
__global__ void __launch_bounds__(256) k_fill_apply(
        const int* __restrict__ rows, const int* __restrict__ cols,
        const float* __restrict__ vals, const float* __restrict__ x,
        const float* __restrict__ gam, const float* __restrict__ bet,
        uint2* __restrict__ xn) {
    int b = blockIdx.x;
    if (b < G_FILL) {
        int e = b * 256 + threadIdx.x;
        if (e < EN) {
            int r = rows[e];
            float w = vals[e];
            int pos = atomicAdd(&g_cursor[r], 1);
            g_ecol[pos] = cols[e];
            g_eval[pos] = w;
            atomicAdd(&g_rowsum[r], w);
        }
        return;
    }
    b -= G_FILL;
    if (b < G_APPL) {
        __shared__ uint2 tile[64 * 33];
        __shared__ float ssc[32], ssf[32];
        if (threadIdx.x < 32) {
            int c = threadIdx.x;
            float sc = gam[c] * g_scale[c];       // gamma * inv-std
            ssc[c] = sc;
            ssf[c] = bet[c] - g_shift[c] * sc;    // beta - mean*sc
        }
        __syncthreads();
        int v0 = b * 64;
        for (int i = threadIdx.x; i < 32 * 64; i += 256) {
            int c = i >> 6, vi = i & 63;
            int v = v0 + vi;
            uint2 q = make_uint2(0u, 0u);
            if (v < VN) {
                float sc = ssc[c], sf = ssf[c];
                float r0 = sc * x[(0 * 32 + c) * VN + v] + sf;
                float r1 = sc * x[(1 * 32 + c) * VN + v] + sf;
                float r2 = sc * x[(2 * 32 + c) * VN + v] + sf;
                float r3 = sc * x[(3 * 32 + c) * VN + v] + sf;
                half2* h = (half2*)&q;
                h[0] = __floats2half2_rn(r0, r1);
                h[1] = __floats2half2_rn(r2, r3);
            }
            tile[vi * 33 + c] = q;
        }
        __syncthreads();
        for (int i = threadIdx.x; i < 32 * 64; i += 256) {
            int vi = i >> 5, c = i & 31;
            int v = v0 + vi;
            if (v < VN) xn[v * 32 + c] = tile[vi * 33 + c];
        }
        return;
    }
    b -= G_APPL;
    // zero deg for next call + reset scan flags
    int i = b * 256 + threadIdx.x;
    if (i < VN) g_deg[i] = 0;
    if (b == 0 && threadIdx.x < NB_SCAN) g_flag[threadIdx.x] = 0;
}

// ---------------- hidden BN finalize (consumes and re-zeroes g_red) ----------------
__global__ void k_finalize(const float* __restrict__ gam, const float* __restrict__ bet, int C) {
    int c = threadIdx.x;
    float sc = 0.f, sf = 0.f;
    if (c < C) {
        float n = (float)VN * (float)BATCH;
        float m = g_red[c] / n;
        float var = g_red[64 + c] / n - m * m;
        sc = gam[c] * rsqrtf(var + BN_EPS);
        sf = bet[c] - m * sc;
    }
    __syncthreads();
    if (c < C) { g_scale[c] = sc; g_shift[c] = sf; }
    g_red[c] = 0.f;
}

// ---------------- fold layer-1 weights ----------------
__global__ void k_fold1(const float* __restrict__ w, const float* __restrict__ bias) {
    int t = blockIdx.x * 256 + threadIdx.x;
    if (t < 16384) {
        int k = t >> 12;
        int c = (t >> 6) & 63;
        float wv = w[t];
        g_wf[t] = (k == 0) ? wv * g_scale[c] : wv;
    }
    if (blockIdx.x == 0 && threadIdx.x < 64) {
        int o = threadIdx.x;
        float s = bias[o];
        for (int c = 0; c < 64; c++) s += w[c * 64 + o] * g_shift[c];
        g_bf[o] = s;
    }
}

// ---------------- fold layer-2 weights + Clenshaw const vectors ----------------
__global__ void k_fold2(const float* __restrict__ w) {
    int t = blockIdx.x * 256 + threadIdx.x;
    if (t < 8192) {
        int c = (t >> 5) & 63;
        g_wf2[t] = w[t] * g_scale[c];
    }
    if (blockIdx.x == 0) {
        __shared__ float su[4 * 32];
        if (threadIdx.x < 128) {
            int k = threadIdx.x >> 5, o = threadIdx.x & 31;
            float u = 0.f;
            for (int c = 0; c < 64; c++) u += w[k * 2048 + c * 32 + o] * g_shift[c];
            su[threadIdx.x] = u;
        }
        __syncthreads();
        if (threadIdx.x < 32) {
            int o = threadIdx.x;
            g_qb2[o]  = su[2 * 32 + o];
            g_pb2[o]  = 2.f * su[3 * 32 + o];
            g_qb1[o]  = su[1 * 32 + o] - su[3 * 32 + o];
            g_qout[o] = su[0 * 32 + o];
        }
    }
}

// ---------------- gather SpMM, fp16, 16 lanes per vertex, runtime row stride/offset -------
// r = coef*(gather of X [AFFX: sc*acc + sf*rowsum]) + s1*Z1[AFFZ1: affine] + s2*Z2
//     [+ q_ch] [+ rowsum*p_ch];  FINAL: + bias + xn, relu, transposed fp32 (B,32,V) store.
template<bool AFFX, bool HASZ1, bool AFFZ1, bool HASZ2, bool HASP, bool HASQ, bool FINAL>
__global__ void __launch_bounds__(256) k_gather(
        float coef, const uint4* __restrict__ X,
        const uint4* __restrict__ Z1, float s1,
        const uint4* __restrict__ Z2, float s2,
        uint4* __restrict__ Y,
        int rowu4, int off,
        const float* __restrict__ qv, const float* __restrict__ pv,
        const float* __restrict__ bias, const uint4* __restrict__ xn,
        float* __restrict__ outF) {
    int vs = threadIdx.x >> 4;
    int j  = threadIdx.x & 15;
    int v  = blockIdx.x * 16 + vs;
    int jj = off + j;

    float r[8] = {0.f, 0.f, 0.f, 0.f, 0.f, 0.f, 0.f, 0.f};
    if (v < VN) {
        int s = g_rowptr[v];
        int e = g_rowptr[v + 1];
        float acc[8] = {0.f, 0.f, 0.f, 0.f, 0.f, 0.f, 0.f, 0.f};
        int i = s;
        for (; i < e && (i & 3); i++) {
            fma8(acc, __ldcs(&g_eval[i]), X[__ldcs(&g_ecol[i]) * rowu4 + jj]);
        }
        for (; i + 4 <= e; i += 4) {
            int4   cc = __ldcs((const int4*)&g_ecol[i]);
            float4 ww = __ldcs((const float4*)&g_eval[i]);
            uint4 q0 = X[cc.x * rowu4 + jj];
            uint4 q1 = X[cc.y * rowu4 + jj];
            uint4 q2 = X[cc.z * rowu4 + jj];
            uint4 q3 = X[cc.w * rowu4 + jj];
            fma8(acc, ww.x, q0);
            fma8(acc, ww.y, q1);
            fma8(acc, ww.z, q2);
            fma8(acc, ww.w, q3);
        }
        for (; i < e; i++) {
            fma8(acc, __ldcs(&g_eval[i]), X[__ldcs(&g_ecol[i]) * rowu4 + jj]);
        }

        float sc0, sc1, sf0, sf1, rs = 0.f;
        if (AFFX || AFFZ1) {
            sc0 = g_scale[2 * jj]; sc1 = g_scale[2 * jj + 1];
            sf0 = g_shift[2 * jj]; sf1 = g_shift[2 * jj + 1];
        }
        if (AFFX || HASP) rs = g_rowsum[v];

        if (AFFX) {
#pragma unroll
            for (int b = 0; b < 4; b++) {
                r[b]     = coef * (sc0 * acc[b]     + sf0 * rs);
                r[4 + b] = coef * (sc1 * acc[4 + b] + sf1 * rs);
            }
        } else {
#pragma unroll
            for (int t = 0; t < 8; t++) r[t] = coef * acc[t];
        }
        if (HASZ1) {
            float z[8];
            unpack8(z, __ldcs(&Z1[v * rowu4 + jj]));
            if (AFFZ1) {
#pragma unroll
                for (int b = 0; b < 4; b++) {
                    r[b]     += s1 * (sc0 * z[b]     + sf0);
                    r[4 + b] += s1 * (sc1 * z[4 + b] + sf1);
                }
            } else {
#pragma unroll
                for (int t = 0; t < 8; t++) r[t] += s1 * z[t];
            }
        }
        if (HASZ2) {
            float z[8];
            unpack8(z, __ldcs(&Z2[v * rowu4 + jj]));
#pragma unroll
            for (int t = 0; t < 8; t++) r[t] += s2 * z[t];
        }
        if (HASQ) {
            float q0 = qv[2 * jj], q1 = qv[2 * jj + 1];
#pragma unroll
            for (int b = 0; b < 4; b++) { r[b] += q0; r[4 + b] += q1; }
        }
        if (HASP) {
            float p0 = pv[2 * jj], p1 = pv[2 * jj + 1];
#pragma unroll
            for (int b = 0; b < 4; b++) { r[b] += rs * p0; r[4 + b] += rs * p1; }
        }
        if (!FINAL) {
            __stcs(&Y[v * rowu4 + jj], pack8(r));
        }
    }

    if (FINAL) {
        // rowu4 == 16, off == 0
        __shared__ float tile[16 * 32 * 4];
        if (v < VN) {
            float xr[8];
            unpack8(xr, xn[v * 16 + jj]);
            float b0 = bias[2 * jj], b1 = bias[2 * jj + 1];
#pragma unroll
            for (int b = 0; b < 4; b++) {
                r[b]     = fmaxf(r[b]     + b0 + xr[b],     0.f);
                r[4 + b] = fmaxf(r[4 + b] + b1 + xr[4 + b], 0.f);
            }
        } else {
#pragma unroll
            for (int t = 0; t < 8; t++) r[t] = 0.f;
        }
#pragma unroll
        for (int b = 0; b < 4; b++) {
            tile[(vs * 32 + 2 * j) * 4 + b]     = r[b];
            tile[(vs * 32 + 2 * j + 1) * 4 + b] = r[4 + b];
        }
        __syncthreads();
        int vl = threadIdx.x & 15;
        int cw = threadIdx.x >> 4;
        int vv = blockIdx.x * 16 + vl;
        if (vv < VN) {
#pragma unroll
            for (int ci = 0; ci < 2; ci++) {
                int c = cw + ci * 16;
#pragma unroll
                for (int b = 0; b < 4; b++) {
                    outF[(b * 32 + c) * VN + vv] = tile[(vl * 32 + c) * 4 + b];
                }
            }
        }
    }
}

// ---------------- combine: R[v,o,:] = relu(bias[o] + sum_kc w[kc,o]*xk[v,kc,:]) fp16 out ---
template<int C, int O, int ITER>
__global__ void __launch_bounds__(256) k_combine(
        const uint4* __restrict__ x0, const uint4* __restrict__ x1,
        const uint4* __restrict__ x2, const uint4* __restrict__ x3,
        const float* __restrict__ w, const float* __restrict__ bias,
        uint2* __restrict__ outR) {
    const int KC = 4 * C;
    const int RU = C / 2;
    const int VPB = 256 / O;
    extern __shared__ char smem[];
    float* sW = (float*)smem;
    uint4* sX = (uint4*)(smem + (size_t)KC * O * sizeof(float));
    __shared__ float sS1[64], sS2[64];
    const int tid = threadIdx.x;

    if (tid < O) { sS1[tid] = 0.f; sS2[tid] = 0.f; }
    for (int i = tid; i < KC * O; i += 256) sW[i] = w[i];

    const int o = tid % O;
    const int vs = tid / O;
    const float bb = bias[o];
    float ls1 = 0.f, ls2 = 0.f;

    for (int it = 0; it < ITER; it++) {
        const int v0 = (blockIdx.x * ITER + it) * VPB;
        __syncthreads();
        for (int i = tid; i < VPB * 4 * RU; i += 256) {
            int vsl = i / (4 * RU);
            int rem = i - vsl * (4 * RU);
            int k = rem / RU, u = rem - k * RU;
            int v = v0 + vsl;
            const uint4* src = (k == 0) ? x0 : (k == 1) ? x1 : (k == 2) ? x2 : x3;
            sX[i] = (v < VN) ? src[v * RU + u] : make_uint4(0u, 0u, 0u, 0u);
        }
        __syncthreads();

        int v = v0 + vs;
        if (v < VN) {
            float4 acc = make_float4(bb, bb, bb, bb);
            const half2* xh = (const half2*)(sX + vs * 4 * RU);
#pragma unroll 8
            for (int kc = 0; kc < KC; kc++) {
                float wv = sW[kc * O + o];
                float2 a = __half22float2(xh[2 * kc]);
                float2 b = __half22float2(xh[2 * kc + 1]);
                acc.x += wv * a.x; acc.y += wv * a.y;
                acc.z += wv * b.x; acc.w += wv * b.y;
            }
            float a = fmaxf(acc.x, 0.f), b = fmaxf(acc.y, 0.f);
            float d = fmaxf(acc.z, 0.f), f = fmaxf(acc.w, 0.f);
            uint2 q;
            half2* h = (half2*)&q;
            h[0] = __floats2half2_rn(a, b);
            h[1] = __floats2half2_rn(d, f);
            outR[v * O + o] = q;
            ls1 += a + b + d + f;
            ls2 += a * a + b * b + d * d + f * f;
        }
    }

    atomicAdd(&sS1[o], ls1);
    atomicAdd(&sS2[o], ls2);
    __syncthreads();
    if (tid < O) {
        atomicAdd(&g_red[tid], sS1[tid]);
        atomicAdd(&g_red[64 + tid], sS2[tid]);
    }
}

// ---------------- combine4 (layer 2): y^_k = wf2_k^T R1, fp16 ----------------
template<int ITER>
__global__ void __launch_bounds__(256) k_combine4(
        const uint4* __restrict__ x, const float* __restrict__ w,
        uint2* __restrict__ y0, uint2* __restrict__ y1,
        uint2* __restrict__ y2, uint2* __restrict__ y3) {
    __shared__ float sW[4 * 64 * 32];
    __shared__ uint4 sX[2 * 32];
    const int tid = threadIdx.x;

    for (int i = tid; i < 4 * 64 * 32; i += 256) sW[i] = w[i];

    const int o2 = tid & 127;
    const int k  = o2 >> 5;
    const int o  = o2 & 31;
    const int vs = tid >> 7;
    uint2* yk = (k == 0) ? y0 : (k == 1) ? y1 : (k == 2) ? y2 : y3;
    const float* wk = sW + k * 64 * 32;

    for (int it = 0; it < ITER; it++) {
        const int v0 = (blockIdx.x * ITER + it) * 2;
        __syncthreads();
        for (int i = tid; i < 2 * 32; i += 256) {
            int vsl = i >> 5, u = i & 31;
            int v = v0 + vsl;
            sX[i] = (v < VN) ? x[v * 32 + u] : make_uint4(0u, 0u, 0u, 0u);
        }
        __syncthreads();

        int v = v0 + vs;
        if (v < VN) {
            float4 acc = make_float4(0.f, 0.f, 0.f, 0.f);
            const half2* xh = (const half2*)(sX + vs * 32);
#pragma unroll 8
            for (int c = 0; c < 64; c++) {
                float wv = wk[c * 32 + o];
                float2 a = __half22float2(xh[2 * c]);
                float2 b = __half22float2(xh[2 * c + 1]);
                acc.x += wv * a.x; acc.y += wv * a.y;
                acc.z += wv * b.x; acc.w += wv * b.y;
            }
            uint2 q;
            half2* h = (half2*)&q;
            h[0] = __floats2half2_rn(acc.x, acc.y);
            h[1] = __floats2half2_rn(acc.z, acc.w);
            yk[v * 32 + o] = q;
        }
    }
}

// ---------------- host orchestration ----------------
extern "C" void kernel_launch(void* const* d_in, const int* in_sizes, int n_in,
                              void* d_out, int out_size) {
    const float* x       = (const float*)d_in[0];
    const int*   ei      = (const int*)  d_in[1];
    const float* vals    = (const float*)d_in[2];
    const float* in_bn_g = (const float*)d_in[3];
    const float* in_bn_b = (const float*)d_in[4];
    const float* in_w    = (const float*)d_in[5];
    const float* in_b    = (const float*)d_in[6];
    const float* h0_bn_g = (const float*)d_in[7];
    const float* h0_bn_b = (const float*)d_in[8];
    const float* h0_w    = (const float*)d_in[9];
    const float* h0_b    = (const float*)d_in[10];
    const float* h1_bn_g = (const float*)d_in[11];
    const float* h1_bn_b = (const float*)d_in[12];
    const float* h1_w    = (const float*)d_in[13];
    const float* h1_b    = (const float*)d_in[14];
    float* out = (float*)d_out;

    const int* rows = ei;
    const int* cols = ei + EN;

    void *pXN, *pR1, *pSA, *pSB, *pSC, *pR0, *pWF, *pBF, *pWF2, *pQB2, *pPB2, *pQB1, *pQO;
    cudaGetSymbolAddress(&pXN, g_XN);
    cudaGetSymbolAddress(&pR1, g_R1);
    cudaGetSymbolAddress(&pSA, g_SA);
    cudaGetSymbolAddress(&pSB, g_SB);
    cudaGetSymbolAddress(&pSC, g_SC);
    cudaGetSymbolAddress(&pR0, g_R0);
    cudaGetSymbolAddress(&pWF, g_wf);
    cudaGetSymbolAddress(&pBF, g_bf);
    cudaGetSymbolAddress(&pWF2, g_wf2);
    cudaGetSymbolAddress(&pQB2, g_qb2);
    cudaGetSymbolAddress(&pPB2, g_pb2);
    cudaGetSymbolAddress(&pQB1, g_qb1);
    cudaGetSymbolAddress(&pQO,  g_qout);
    uint4* XN = (uint4*)pXN;
    uint4* R1 = (uint4*)pR1;
    uint4* SA = (uint4*)pSA;
    uint4* SB = (uint4*)pSB;
    uint4* SC = (uint4*)pSC;
    uint4* R0 = (uint4*)pR0;
    const float* WF  = (const float*)pWF;
    const float* BF  = (const float*)pBF;
    const float* WF2 = (const float*)pWF2;
    const float* QB2 = (const float*)pQB2;
    const float* PB2 = (const float*)pPB2;
    const float* QB1 = (const float*)pQB1;
    const float* QO  = (const float*)pQO;

    cudaFuncSetAttribute(k_combine<32, 64, 4>, cudaFuncAttributeMaxDynamicSharedMemorySize, 36864);
    cudaFuncSetAttribute(k_combine<64, 64, 4>, cudaFuncAttributeMaxDynamicSharedMemorySize, 73728);

    const int gG   = (VN + 15) / 16;   // gather grid (16 vertices/block)
    const int gCMB = (VN + 15) / 16;

    // ---- launches 1-3: CSR build + input BN, compressed ----
    k_hist_stats<<<G_HIST + G_RS + G_STAT, 256>>>(rows, x);
    k_scan<<<NB_SCAN + 1, 1024>>>();
    k_fill_apply<<<G_FILL + G_APPL + G_ZDEG, 256>>>(rows, cols, vals, x, in_bn_g, in_bn_b, (uint2*)pXN);

    // ---- layer 0: C=32 -> O=64 (launch 4 = first gather, ncu-profiled) ----
    k_gather<0,0,0,0,0,0,0><<<gG, 256>>>(1.f, XN, nullptr, 0.f, nullptr, 0.f, SA, 16, 0, nullptr, nullptr, nullptr, nullptr, nullptr);
    k_gather<0,1,0,0,0,0,0><<<gG, 256>>>(2.f, SA, XN, -1.f, nullptr, 0.f, SB, 16, 0, nullptr, nullptr, nullptr, nullptr, nullptr);
    k_gather<0,1,0,0,0,0,0><<<gG, 256>>>(2.f, SB, SA, -1.f, nullptr, 0.f, SC, 16, 0, nullptr, nullptr, nullptr, nullptr, nullptr);
    k_combine<32, 64, 4><<<gCMB, 256, 36864>>>(XN, SA, SB, SC, in_w, in_b, (uint2*)pR0);

    // ---- hidden-0 BN folded ----
    k_finalize<<<1, 128>>>(h0_bn_g, h0_bn_b, 64);
    k_fold1<<<64, 256>>>(h0_w, h0_b);

    // ---- layer 1: C=64 -> O=64; channel-split gathers (L2-fitting halves) ----
    k_gather<1,0,0,0,0,0,0><<<gG, 256>>>(1.f, R0, nullptr, 0.f, nullptr, 0.f, SA, 32, 0,  nullptr, nullptr, nullptr, nullptr, nullptr);
    k_gather<1,0,0,0,0,0,0><<<gG, 256>>>(1.f, R0, nullptr, 0.f, nullptr, 0.f, SA, 32, 16, nullptr, nullptr, nullptr, nullptr, nullptr);
    k_gather<0,1,1,0,0,0,0><<<gG, 256>>>(2.f, SA, R0, -1.f, nullptr, 0.f, SB, 32, 0,  nullptr, nullptr, nullptr, nullptr, nullptr);
    k_gather<0,1,1,0,0,0,0><<<gG, 256>>>(2.f, SA, R0, -1.f, nullptr, 0.f, SB, 32, 16, nullptr, nullptr, nullptr, nullptr, nullptr);
    k_gather<0,1,0,0,0,0,0><<<gG, 256>>>(2.f, SB, SA, -1.f, nullptr, 0.f, SC, 32, 0,  nullptr, nullptr, nullptr, nullptr, nullptr);
    k_gather<0,1,0,0,0,0,0><<<gG, 256>>>(2.f, SB, SA, -1.f, nullptr, 0.f, SC, 32, 16, nullptr, nullptr, nullptr, nullptr, nullptr);
    k_combine<64, 64, 4><<<gCMB, 256, 73728>>>(R0, SA, SB, SC, WF, BF, (uint2*)pR1);

    // ---- hidden-1 BN folded ----
    k_finalize<<<1, 128>>>(h1_bn_g, h1_bn_b, 64);
    k_fold2<<<32, 256>>>(h1_w);

    // ---- layer 2 via Clenshaw on folded y^_k (width 32) ----
    k_combine4<8><<<(VN + 15) / 16, 256>>>(R1, WF2, (uint2*)pSA, (uint2*)pSB, (uint2*)pSC, (uint2*)pR0);
    // b2 = 2 L y^3 + y^2 + rs*(2u3) + u2   -> R1
    k_gather<0,1,0,0,1,1,0><<<gG, 256>>>(2.f, R0, SC, 1.f, nullptr, 0.f, R1, 16, 0, QB2, PB2, nullptr, nullptr, nullptr);
    // b1 = 2 L b2 + y^1 - y^3 + (u1-u3)    -> SC
    k_gather<0,1,0,1,0,1,0><<<gG, 256>>>(2.f, R1, SB, 1.f, R0, -1.f, SC, 16, 0, QB1, nullptr, nullptr, nullptr, nullptr);
    // out = relu(L b1 + y^0 - b2 + u0 + bias + xn), transposed to (B,32,V)
    k_gather<0,1,0,1,0,1,1><<<gG, 256>>>(1.f, SC, SA, 1.f, R1, -1.f, nullptr, 16, 0, QO, nullptr, h1_b, XN, out);
}

// round 9
// speedup vs baseline: 1.0557x; 1.0557x over previous
#include <cuda_runtime.h>
#include <cuda_fp16.h>

#define VN 100000
#define EN 1600000
#define BATCH 4
#define BN_EPS 1e-5f
#define NB_SCAN 98            // ceil(VN/1024)
#define G_HIST 6250           // (EN+255)/256
#define G_RS   391            // (VN+255)/256
#define G_STAT 2048           // 32 channels x 64 blocks
#define G_FILL 6250
#define G_APPL 1563           // (VN+63)/64
#define G_ZDEG 391

// ---------------- static device scratch (no allocations allowed) ----------------
// feature tensors fp16, layout (V, C, B): element (v,c,b) at ((v*C+c)*4+b)
__device__ __align__(256) __half g_XN[VN * 32 * BATCH];   // BN'ed input (x0 of layer 0)
__device__ __align__(256) __half g_R1[VN * 64 * BATCH];   // relu(H1) / b2
__device__ __align__(256) __half g_SA[VN * 64 * BATCH];   // x1 / y0^
__device__ __align__(256) __half g_SB[VN * 64 * BATCH];   // x2 / y1^
__device__ __align__(256) __half g_SC[VN * 64 * BATCH];   // x3 / y2^ / b1
__device__ __align__(256) __half g_R0[VN * 64 * BATCH];   // relu(H0) / y3^
__device__ float g_red[128];
__device__ float g_scale[64];
__device__ float g_shift[64];

// folded weights / constant vectors
__device__ float g_wf[4 * 64 * 64];
__device__ float g_bf[64];
__device__ float g_wf2[4 * 64 * 32];
__device__ float g_qb2[32], g_pb2[32], g_qb1[32], g_qout[32];

// CSR scratch
__device__ __align__(256) int   g_deg[VN];
__device__ __align__(256) int   g_rowptr[VN + 1];
__device__ __align__(256) int   g_cursor[VN];
__device__ __align__(256) float g_rowsum[VN];
__device__ __align__(256) int   g_ecol[EN];
__device__ __align__(256) float g_eval[EN];

// decoupled-lookback scan state
__device__ volatile int g_agg[NB_SCAN];
__device__ volatile int g_incl[NB_SCAN];
__device__ volatile int g_flag[NB_SCAN];

// ---------------- fp16 helpers (8 values = 2 channels x 4 batch) ----------------
__device__ __forceinline__ void fma8(float* acc, float w, uint4 q) {
    half2* h = (half2*)&q;
#pragma unroll
    for (int t = 0; t < 4; t++) {
        float2 f = __half22float2(h[t]);
        acc[2 * t]     += w * f.x;
        acc[2 * t + 1] += w * f.y;
    }
}
__device__ __forceinline__ void unpack8(float* z, uint4 q) {
    half2* h = (half2*)&q;
#pragma unroll
    for (int t = 0; t < 4; t++) {
        float2 f = __half22float2(h[t]);
        z[2 * t] = f.x; z[2 * t + 1] = f.y;
    }
}
__device__ __forceinline__ uint4 pack8(const float* r) {
    uint4 q;
    half2* h = (half2*)&q;
#pragma unroll
    for (int t = 0; t < 4; t++) h[t] = __floats2half2_rn(r[2 * t], r[2 * t + 1]);
    return q;
}

// ================= launch 1: edge histogram + input BN stats + zero rowsum =================
__global__ void __launch_bounds__(256) k_hist_stats(const int* __restrict__ rows,
                                                    const float* __restrict__ x) {
    int b = blockIdx.x;
    if (b < G_HIST) {
        int e = b * 256 + threadIdx.x;
        if (e < EN) atomicAdd(&g_deg[rows[e]], 1);
        return;
    }
    b -= G_HIST;
    if (b < G_RS) {
        int i = b * 256 + threadIdx.x;
        if (i < VN) g_rowsum[i] = 0.f;
        return;
    }
    b -= G_RS;
    int c = b >> 6;
    int chunk = b & 63;
    float s1 = 0.f, s2 = 0.f;
    for (int v = chunk * 256 + threadIdx.x; v < VN; v += 64 * 256) {
#pragma unroll
        for (int bb = 0; bb < BATCH; bb++) {
            float t = x[(bb * 32 + c) * VN + v];
            s1 += t; s2 += t * t;
        }
    }
    __shared__ float sh1[256], sh2[256];
    sh1[threadIdx.x] = s1; sh2[threadIdx.x] = s2;
    __syncthreads();
    for (int off = 128; off > 0; off >>= 1) {
        if (threadIdx.x < off) {
            sh1[threadIdx.x] += sh1[threadIdx.x + off];
            sh2[threadIdx.x] += sh2[threadIdx.x + off];
        }
        __syncthreads();
    }
    if (threadIdx.x == 0) {
        atomicAdd(&g_red[c], sh1[0]);
        atomicAdd(&g_red[64 + c], sh2[0]);
    }
}

// ================= launch 2: decoupled-lookback scan + input BN finalize =================
__global__ void __launch_bounds__(1024) k_scan() {
    int b = blockIdx.x;
    int t = threadIdx.x;
    if (b == NB_SCAN) {
        if (t < 32) {
            float n = (float)VN * (float)BATCH;
            float m = g_red[t] / n;
            float var = g_red[64 + t] / n - m * m;
            g_scale[t] = rsqrtf(var + BN_EPS);   // raw inv-std
            g_shift[t] = m;                      // raw mean
        }
        __syncthreads();
        if (t < 128) g_red[t] = 0.f;
        if (t == 0) g_rowptr[VN] = EN;
        return;
    }
    __shared__ int sh[1024];
    int i = b * 1024 + t;
    int val = (i < VN) ? g_deg[i] : 0;
    sh[t] = val;
    __syncthreads();
    for (int off = 1; off < 1024; off <<= 1) {
        int tmp = (t >= off) ? sh[t - off] : 0;
        __syncthreads();
        sh[t] += tmp;
        __syncthreads();
    }
    __shared__ int s_prefix;
    if (t == 0) {
        int total = sh[1023];
        int prefix = 0;
        if (b == 0) {
            g_incl[0] = total;
            __threadfence();
            g_flag[0] = 2;
        } else {
            g_agg[b] = total;
            __threadfence();
            g_flag[b] = 1;
            int j = b - 1;
            while (true) {
                int f;
                while ((f = g_flag[j]) == 0) { }
                if (f == 2) { prefix += g_incl[j]; break; }
                prefix += g_agg[j];
                j--;
            }
            g_incl[b] = prefix + total;
            __threadfence();
            g_flag[b] = 2;
        }
        s_prefix = prefix;
    }
    __syncthreads();
    if (i < VN) {
        int excl = s_prefix + sh[t] - val;
        g_rowptr[i] = excl;
        g_cursor[i] = excl;
    }
}

// ================= launch 3: CSR fill + input BN apply/transpose + zero deg/flags =========
__global__ void __launch_bounds__(256) k_fill_apply(
        const int* __restrict__ rows, const int* __restrict__ cols,
        const float* __restrict__ vals, const float* __restrict__ x,
        const float* __restrict__ gam, const float* __restrict__ bet,
        uint2* __restrict__ xn) {
    int b = blockIdx.x;
    if (b < G_FILL) {
        int e = b * 256 + threadIdx.x;
        if (e < EN) {
            int r = rows[e];
            float w = vals[e];
            int pos = atomicAdd(&g_cursor[r], 1);
            g_ecol[pos] = cols[e];
            g_eval[pos] = w;
            atomicAdd(&g_rowsum[r], w);
        }
        return;
    }
    b -= G_FILL;
    if (b < G_APPL) {
        __shared__ uint2 tile[64 * 33];
        __shared__ float ssc[32], ssf[32];
        if (threadIdx.x < 32) {
            int c = threadIdx.x;
            float sc = gam[c] * g_scale[c];
            ssc[c] = sc;
            ssf[c] = bet[c] - g_shift[c] * sc;
        }
        __syncthreads();
        int v0 = b * 64;
        for (int i = threadIdx.x; i < 32 * 64; i += 256) {
            int c = i >> 6, vi = i & 63;
            int v = v0 + vi;
            uint2 q = make_uint2(0u, 0u);
            if (v < VN) {
                float sc = ssc[c], sf = ssf[c];
                float r0 = sc * x[(0 * 32 + c) * VN + v] + sf;
                float r1 = sc * x[(1 * 32 + c) * VN + v] + sf;
                float r2 = sc * x[(2 * 32 + c) * VN + v] + sf;
                float r3 = sc * x[(3 * 32 + c) * VN + v] + sf;
                half2* h = (half2*)&q;
                h[0] = __floats2half2_rn(r0, r1);
                h[1] = __floats2half2_rn(r2, r3);
            }
            tile[vi * 33 + c] = q;
        }
        __syncthreads();
        for (int i = threadIdx.x; i < 32 * 64; i += 256) {
            int vi = i >> 5, c = i & 31;
            int v = v0 + vi;
            if (v < VN) xn[v * 32 + c] = tile[vi * 33 + c];
        }
        return;
    }
    b -= G_APPL;
    int i = b * 256 + threadIdx.x;
    if (i < VN) g_deg[i] = 0;
    if (b == 0 && threadIdx.x < NB_SCAN) g_flag[threadIdx.x] = 0;
}

// ---------------- hidden BN finalize ----------------
__global__ void k_finalize(const float* __restrict__ gam, const float* __restrict__ bet, int C) {
    int c = threadIdx.x;
    float sc = 0.f, sf = 0.f;
    if (c < C) {
        float n = (float)VN * (float)BATCH;
        float m = g_red[c] / n;
        float var = g_red[64 + c] / n - m * m;
        sc = gam[c] * rsqrtf(var + BN_EPS);
        sf = bet[c] - m * sc;
    }
    __syncthreads();
    if (c < C) { g_scale[c] = sc; g_shift[c] = sf; }
    g_red[c] = 0.f;
}

// ---------------- fold layer-1 weights ----------------
__global__ void k_fold1(const float* __restrict__ w, const float* __restrict__ bias) {
    int t = blockIdx.x * 256 + threadIdx.x;
    if (t < 16384) {
        int k = t >> 12;
        int c = (t >> 6) & 63;
        float wv = w[t];
        g_wf[t] = (k == 0) ? wv * g_scale[c] : wv;
    }
    if (blockIdx.x == 0 && threadIdx.x < 64) {
        int o = threadIdx.x;
        float s = bias[o];
        for (int c = 0; c < 64; c++) s += w[c * 64 + o] * g_shift[c];
        g_bf[o] = s;
    }
}

// ---------------- fold layer-2 weights + Clenshaw const vectors ----------------
__global__ void k_fold2(const float* __restrict__ w) {
    int t = blockIdx.x * 256 + threadIdx.x;
    if (t < 8192) {
        int c = (t >> 5) & 63;
        g_wf2[t] = w[t] * g_scale[c];
    }
    if (blockIdx.x == 0) {
        __shared__ float su[4 * 32];
        if (threadIdx.x < 128) {
            int k = threadIdx.x >> 5, o = threadIdx.x & 31;
            float u = 0.f;
            for (int c = 0; c < 64; c++) u += w[k * 2048 + c * 32 + o] * g_shift[c];
            su[threadIdx.x] = u;
        }
        __syncthreads();
        if (threadIdx.x < 32) {
            int o = threadIdx.x;
            g_qb2[o]  = su[2 * 32 + o];
            g_pb2[o]  = 2.f * su[3 * 32 + o];
            g_qb1[o]  = su[1 * 32 + o] - su[3 * 32 + o];
            g_qout[o] = su[0 * 32 + o];
        }
    }
}

// ---------------- gather SpMM, fp16, RU4 lanes per vertex (template stride) ----------------
// r = coef*(gather of X [AFFX: sc*acc + sf*rowsum]) + s1*Z1[AFFZ1: affine] + s2*Z2
//     [+ q_ch] [+ rowsum*p_ch];  FINAL: + bias + xn, relu, transposed fp32 (B,32,V) store.
template<int RU4, bool AFFX, bool HASZ1, bool AFFZ1, bool HASZ2, bool HASP, bool HASQ, bool FINAL>
__global__ void __launch_bounds__(256) k_gather(
        float coef, const uint4* __restrict__ X,
        const uint4* __restrict__ Z1, float s1,
        const uint4* __restrict__ Z2, float s2,
        uint4* __restrict__ Y,
        const float* __restrict__ qv, const float* __restrict__ pv,
        const float* __restrict__ bias, const uint4* __restrict__ xn,
        float* __restrict__ outF) {
    const int VPB = 256 / RU4;
    int vs = threadIdx.x / RU4;
    int j  = threadIdx.x % RU4;
    int v  = blockIdx.x * VPB + vs;

    float r[8] = {0.f, 0.f, 0.f, 0.f, 0.f, 0.f, 0.f, 0.f};
    if (v < VN) {
        int s = g_rowptr[v];
        int e = g_rowptr[v + 1];
        float acc[8] = {0.f, 0.f, 0.f, 0.f, 0.f, 0.f, 0.f, 0.f};
        int i = s;
        for (; i < e && (i & 3); i++) {
            fma8(acc, __ldcs(&g_eval[i]), X[__ldcs(&g_ecol[i]) * RU4 + j]);
        }
        for (; i + 8 <= e; i += 8) {
            int4   ca = __ldcs((const int4*)&g_ecol[i]);
            int4   cb = __ldcs((const int4*)&g_ecol[i + 4]);
            float4 wa = __ldcs((const float4*)&g_eval[i]);
            float4 wb = __ldcs((const float4*)&g_eval[i + 4]);
            uint4 q0 = X[ca.x * RU4 + j];
            uint4 q1 = X[ca.y * RU4 + j];
            uint4 q2 = X[ca.z * RU4 + j];
            uint4 q3 = X[ca.w * RU4 + j];
            uint4 q4 = X[cb.x * RU4 + j];
            uint4 q5 = X[cb.y * RU4 + j];
            uint4 q6 = X[cb.z * RU4 + j];
            uint4 q7 = X[cb.w * RU4 + j];
            fma8(acc, wa.x, q0);
            fma8(acc, wa.y, q1);
            fma8(acc, wa.z, q2);
            fma8(acc, wa.w, q3);
            fma8(acc, wb.x, q4);
            fma8(acc, wb.y, q5);
            fma8(acc, wb.z, q6);
            fma8(acc, wb.w, q7);
        }
        for (; i + 4 <= e; i += 4) {
            int4   cc = __ldcs((const int4*)&g_ecol[i]);
            float4 ww = __ldcs((const float4*)&g_eval[i]);
            uint4 q0 = X[cc.x * RU4 + j];
            uint4 q1 = X[cc.y * RU4 + j];
            uint4 q2 = X[cc.z * RU4 + j];
            uint4 q3 = X[cc.w * RU4 + j];
            fma8(acc, ww.x, q0);
            fma8(acc, ww.y, q1);
            fma8(acc, ww.z, q2);
            fma8(acc, ww.w, q3);
        }
        for (; i < e; i++) {
            fma8(acc, __ldcs(&g_eval[i]), X[__ldcs(&g_ecol[i]) * RU4 + j]);
        }

        float sc0, sc1, sf0, sf1, rs = 0.f;
        if (AFFX || AFFZ1) {
            sc0 = g_scale[2 * j]; sc1 = g_scale[2 * j + 1];
            sf0 = g_shift[2 * j]; sf1 = g_shift[2 * j + 1];
        }
        if (AFFX || HASP) rs = g_rowsum[v];

        if (AFFX) {
#pragma unroll
            for (int b = 0; b < 4; b++) {
                r[b]     = coef * (sc0 * acc[b]     + sf0 * rs);
                r[4 + b] = coef * (sc1 * acc[4 + b] + sf1 * rs);
            }
        } else {
#pragma unroll
            for (int t = 0; t < 8; t++) r[t] = coef * acc[t];
        }
        if (HASZ1) {
            float z[8];
            unpack8(z, __ldcs(&Z1[v * RU4 + j]));
            if (AFFZ1) {
#pragma unroll
                for (int b = 0; b < 4; b++) {
                    r[b]     += s1 * (sc0 * z[b]     + sf0);
                    r[4 + b] += s1 * (sc1 * z[4 + b] + sf1);
                }
            } else {
#pragma unroll
                for (int t = 0; t < 8; t++) r[t] += s1 * z[t];
            }
        }
        if (HASZ2) {
            float z[8];
            unpack8(z, __ldcs(&Z2[v * RU4 + j]));
#pragma unroll
            for (int t = 0; t < 8; t++) r[t] += s2 * z[t];
        }
        if (HASQ) {
            float q0 = qv[2 * j], q1 = qv[2 * j + 1];
#pragma unroll
            for (int b = 0; b < 4; b++) { r[b] += q0; r[4 + b] += q1; }
        }
        if (HASP) {
            float p0 = pv[2 * j], p1 = pv[2 * j + 1];
#pragma unroll
            for (int b = 0; b < 4; b++) { r[b] += rs * p0; r[4 + b] += rs * p1; }
        }
        if (!FINAL) {
            __stcs(&Y[v * RU4 + j], pack8(r));
        }
    }

    if (FINAL) {
        // RU4 == 16, VPB == 16
        __shared__ float tile[16 * 32 * 4];
        if (v < VN) {
            float xr[8];
            unpack8(xr, xn[v * 16 + j]);
            float b0 = bias[2 * j], b1 = bias[2 * j + 1];
#pragma unroll
            for (int b = 0; b < 4; b++) {
                r[b]     = fmaxf(r[b]     + b0 + xr[b],     0.f);
                r[4 + b] = fmaxf(r[4 + b] + b1 + xr[4 + b], 0.f);
            }
        } else {
#pragma unroll
            for (int t = 0; t < 8; t++) r[t] = 0.f;
        }
#pragma unroll
        for (int b = 0; b < 4; b++) {
            tile[(vs * 32 + 2 * j) * 4 + b]     = r[b];
            tile[(vs * 32 + 2 * j + 1) * 4 + b] = r[4 + b];
        }
        __syncthreads();
        int vl = threadIdx.x & 15;
        int cw = threadIdx.x >> 4;
        int vv = blockIdx.x * 16 + vl;
        if (vv < VN) {
#pragma unroll
            for (int ci = 0; ci < 2; ci++) {
                int c = cw + ci * 16;
#pragma unroll
                for (int b = 0; b < 4; b++) {
                    outF[(b * 32 + c) * VN + vv] = tile[(vl * 32 + c) * 4 + b];
                }
            }
        }
    }
}

// ---------------- combine: R[v,o,:] = relu(bias[o] + sum_kc w[kc,o]*xk[v,kc,:]) fp16 out ---
template<int C, int O, int ITER>
__global__ void __launch_bounds__(256) k_combine(
        const uint4* __restrict__ x0, const uint4* __restrict__ x1,
        const uint4* __restrict__ x2, const uint4* __restrict__ x3,
        const float* __restrict__ w, const float* __restrict__ bias,
        uint2* __restrict__ outR) {
    const int KC = 4 * C;
    const int RU = C / 2;
    const int VPB = 256 / O;
    extern __shared__ char smem[];
    float* sW = (float*)smem;
    uint4* sX = (uint4*)(smem + (size_t)KC * O * sizeof(float));
    __shared__ float sS1[64], sS2[64];
    const int tid = threadIdx.x;

    if (tid < O) { sS1[tid] = 0.f; sS2[tid] = 0.f; }
    for (int i = tid; i < KC * O; i += 256) sW[i] = w[i];

    const int o = tid % O;
    const int vs = tid / O;
    const float bb = bias[o];
    float ls1 = 0.f, ls2 = 0.f;

    for (int it = 0; it < ITER; it++) {
        const int v0 = (blockIdx.x * ITER + it) * VPB;
        __syncthreads();
        for (int i = tid; i < VPB * 4 * RU; i += 256) {
            int vsl = i / (4 * RU);
            int rem = i - vsl * (4 * RU);
            int k = rem / RU, u = rem - k * RU;
            int v = v0 + vsl;
            const uint4* src = (k == 0) ? x0 : (k == 1) ? x1 : (k == 2) ? x2 : x3;
            sX[i] = (v < VN) ? src[v * RU + u] : make_uint4(0u, 0u, 0u, 0u);
        }
        __syncthreads();

        int v = v0 + vs;
        if (v < VN) {
            float4 acc = make_float4(bb, bb, bb, bb);
            const half2* xh = (const half2*)(sX + vs * 4 * RU);
#pragma unroll 8
            for (int kc = 0; kc < KC; kc++) {
                float wv = sW[kc * O + o];
                float2 a = __half22float2(xh[2 * kc]);
                float2 b = __half22float2(xh[2 * kc + 1]);
                acc.x += wv * a.x; acc.y += wv * a.y;
                acc.z += wv * b.x; acc.w += wv * b.y;
            }
            float a = fmaxf(acc.x, 0.f), b = fmaxf(acc.y, 0.f);
            float d = fmaxf(acc.z, 0.f), f = fmaxf(acc.w, 0.f);
            uint2 q;
            half2* h = (half2*)&q;
            h[0] = __floats2half2_rn(a, b);
            h[1] = __floats2half2_rn(d, f);
            outR[v * O + o] = q;
            ls1 += a + b + d + f;
            ls2 += a * a + b * b + d * d + f * f;
        }
    }

    atomicAdd(&sS1[o], ls1);
    atomicAdd(&sS2[o], ls2);
    __syncthreads();
    if (tid < O) {
        atomicAdd(&g_red[tid], sS1[tid]);
        atomicAdd(&g_red[64 + tid], sS2[tid]);
    }
}

// ---------------- combine4 (layer 2): y^_k = wf2_k^T R1, fp16 ----------------
template<int ITER>
__global__ void __launch_bounds__(256) k_combine4(
        const uint4* __restrict__ x, const float* __restrict__ w,
        uint2* __restrict__ y0, uint2* __restrict__ y1,
        uint2* __restrict__ y2, uint2* __restrict__ y3) {
    __shared__ float sW[4 * 64 * 32];
    __shared__ uint4 sX[2 * 32];
    const int tid = threadIdx.x;

    for (int i = tid; i < 4 * 64 * 32; i += 256) sW[i] = w[i];

    const int o2 = tid & 127;
    const int k  = o2 >> 5;
    const int o  = o2 & 31;
    const int vs = tid >> 7;
    uint2* yk = (k == 0) ? y0 : (k == 1) ? y1 : (k == 2) ? y2 : y3;
    const float* wk = sW + k * 64 * 32;

    for (int it = 0; it < ITER; it++) {
        const int v0 = (blockIdx.x * ITER + it) * 2;
        __syncthreads();
        for (int i = tid; i < 2 * 32; i += 256) {
            int vsl = i >> 5, u = i & 31;
            int v = v0 + vsl;
            sX[i] = (v < VN) ? x[v * 32 + u] : make_uint4(0u, 0u, 0u, 0u);
        }
        __syncthreads();

        int v = v0 + vs;
        if (v < VN) {
            float4 acc = make_float4(0.f, 0.f, 0.f, 0.f);
            const half2* xh = (const half2*)(sX + vs * 32);
#pragma unroll 8
            for (int c = 0; c < 64; c++) {
                float wv = wk[c * 32 + o];
                float2 a = __half22float2(xh[2 * c]);
                float2 b = __half22float2(xh[2 * c + 1]);
                acc.x += wv * a.x; acc.y += wv * a.y;
                acc.z += wv * b.x; acc.w += wv * b.y;
            }
            uint2 q;
            half2* h = (half2*)&q;
            h[0] = __floats2half2_rn(acc.x, acc.y);
            h[1] = __floats2half2_rn(acc.z, acc.w);
            yk[v * 32 + o] = q;
        }
    }
}

// ---------------- host orchestration ----------------
extern "C" void kernel_launch(void* const* d_in, const int* in_sizes, int n_in,
                              void* d_out, int out_size) {
    const float* x       = (const float*)d_in[0];
    const int*   ei      = (const int*)  d_in[1];
    const float* vals    = (const float*)d_in[2];
    const float* in_bn_g = (const float*)d_in[3];
    const float* in_bn_b = (const float*)d_in[4];
    const float* in_w    = (const float*)d_in[5];
    const float* in_b    = (const float*)d_in[6];
    const float* h0_bn_g = (const float*)d_in[7];
    const float* h0_bn_b = (const float*)d_in[8];
    const float* h0_w    = (const float*)d_in[9];
    const float* h0_b    = (const float*)d_in[10];
    const float* h1_bn_g = (const float*)d_in[11];
    const float* h1_bn_b = (const float*)d_in[12];
    const float* h1_w    = (const float*)d_in[13];
    const float* h1_b    = (const float*)d_in[14];
    float* out = (float*)d_out;

    const int* rows = ei;
    const int* cols = ei + EN;

    void *pXN, *pR1, *pSA, *pSB, *pSC, *pR0, *pWF, *pBF, *pWF2, *pQB2, *pPB2, *pQB1, *pQO;
    cudaGetSymbolAddress(&pXN, g_XN);
    cudaGetSymbolAddress(&pR1, g_R1);
    cudaGetSymbolAddress(&pSA, g_SA);
    cudaGetSymbolAddress(&pSB, g_SB);
    cudaGetSymbolAddress(&pSC, g_SC);
    cudaGetSymbolAddress(&pR0, g_R0);
    cudaGetSymbolAddress(&pWF, g_wf);
    cudaGetSymbolAddress(&pBF, g_bf);
    cudaGetSymbolAddress(&pWF2, g_wf2);
    cudaGetSymbolAddress(&pQB2, g_qb2);
    cudaGetSymbolAddress(&pPB2, g_pb2);
    cudaGetSymbolAddress(&pQB1, g_qb1);
    cudaGetSymbolAddress(&pQO,  g_qout);
    uint4* XN = (uint4*)pXN;
    uint4* R1 = (uint4*)pR1;
    uint4* SA = (uint4*)pSA;
    uint4* SB = (uint4*)pSB;
    uint4* SC = (uint4*)pSC;
    uint4* R0 = (uint4*)pR0;
    const float* WF  = (const float*)pWF;
    const float* BF  = (const float*)pBF;
    const float* WF2 = (const float*)pWF2;
    const float* QB2 = (const float*)pQB2;
    const float* PB2 = (const float*)pPB2;
    const float* QB1 = (const float*)pQB1;
    const float* QO  = (const float*)pQO;

    cudaFuncSetAttribute(k_combine<32, 64, 4>, cudaFuncAttributeMaxDynamicSharedMemorySize, 36864);
    cudaFuncSetAttribute(k_combine<64, 64, 4>, cudaFuncAttributeMaxDynamicSharedMemorySize, 73728);

    const int gG32 = (VN + 15) / 16;   // RU4=16 gather grid
    const int gG64 = (VN + 7) / 8;     // RU4=32 gather grid
    const int gCMB = (VN + 15) / 16;

    // ---- launches 1-3: CSR build + input BN, compressed ----
    k_hist_stats<<<G_HIST + G_RS + G_STAT, 256>>>(rows, x);
    k_scan<<<NB_SCAN + 1, 1024>>>();
    k_fill_apply<<<G_FILL + G_APPL + G_ZDEG, 256>>>(rows, cols, vals, x, in_bn_g, in_bn_b, (uint2*)pXN);

    // ---- layer 0: C=32 -> O=64 (launch 4 = first gather, ncu-profiled) ----
    k_gather<16,0,0,0,0,0,0,0><<<gG32, 256>>>(1.f, XN, nullptr, 0.f, nullptr, 0.f, SA, nullptr, nullptr, nullptr, nullptr, nullptr);
    k_gather<16,0,1,0,0,0,0,0><<<gG32, 256>>>(2.f, SA, XN, -1.f, nullptr, 0.f, SB, nullptr, nullptr, nullptr, nullptr, nullptr);
    k_gather<16,0,1,0,0,0,0,0><<<gG32, 256>>>(2.f, SB, SA, -1.f, nullptr, 0.f, SC, nullptr, nullptr, nullptr, nullptr, nullptr);
    k_combine<32, 64, 4><<<gCMB, 256, 36864>>>(XN, SA, SB, SC, in_w, in_b, (uint2*)pR0);

    // ---- hidden-0 BN folded ----
    k_finalize<<<1, 128>>>(h0_bn_g, h0_bn_b, 64);
    k_fold1<<<64, 256>>>(h0_w, h0_b);

    // ---- layer 1: C=64 -> O=64, single-pass gathers; x0 = affine(R0) on the fly ----
    k_gather<32,1,0,0,0,0,0,0><<<gG64, 256>>>(1.f, R0, nullptr, 0.f, nullptr, 0.f, SA, nullptr, nullptr, nullptr, nullptr, nullptr);
    k_gather<32,0,1,1,0,0,0,0><<<gG64, 256>>>(2.f, SA, R0, -1.f, nullptr, 0.f, SB, nullptr, nullptr, nullptr, nullptr, nullptr);
    k_gather<32,0,1,0,0,0,0,0><<<gG64, 256>>>(2.f, SB, SA, -1.f, nullptr, 0.f, SC, nullptr, nullptr, nullptr, nullptr, nullptr);
    k_combine<64, 64, 4><<<gCMB, 256, 73728>>>(R0, SA, SB, SC, WF, BF, (uint2*)pR1);

    // ---- hidden-1 BN folded ----
    k_finalize<<<1, 128>>>(h1_bn_g, h1_bn_b, 64);
    k_fold2<<<32, 256>>>(h1_w);

    // ---- layer 2 via Clenshaw on folded y^_k (width 32) ----
    k_combine4<8><<<(VN + 15) / 16, 256>>>(R1, WF2, (uint2*)pSA, (uint2*)pSB, (uint2*)pSC, (uint2*)pR0);
    // b2 = 2 L y^3 + y^2 + rs*(2u3) + u2   -> R1
    k_gather<16,0,1,0,0,1,1,0><<<gG32, 256>>>(2.f, R0, SC, 1.f, nullptr, 0.f, R1, QB2, PB2, nullptr, nullptr, nullptr);
    // b1 = 2 L b2 + y^1 - y^3 + (u1-u3)    -> SC
    k_gather<16,0,1,0,1,0,1,0><<<gG32, 256>>>(2.f, R1, SB, 1.f, R0, -1.f, SC, QB1, nullptr, nullptr, nullptr, nullptr);
    // out = relu(L b1 + y^0 - b2 + u0 + bias + xn), transposed to (B,32,V)
    k_gather<16,0,1,0,1,0,1,1><<<gG32, 256>>>(1.f, SC, SA, 1.f, R1, -1.f, nullptr, QO, nullptr, h1_b, XN, out);
}